// round 10
// baseline (speedup 1.0000x reference)
#include <cuda_runtime.h>
#include <cuda_bf16.h>
#include <cstdint>

#define OPC 31
#define BB 64
#define DD 1024
#define NSTEP 16

// ---- GEMM tiling ----
#define KT 64              // k-chunk (over d)
#define NT 64              // n-tile width
#define AP 72              // A smem row stride (144B = 9*16B, ldmatrix conflict-free)
#define BP 72              // B smem row stride (144B)
#define A_BYTES (128 * AP * 2)            // 18432
#define B_BYTES (KT * BP * 2)             // 9216 per (hi|lo)
#define STAGE_BYTES (A_BYTES + 2 * B_BYTES)  // 36864
#define NSTAGE 5
#define GEMM_SMEM (NSTAGE * STAGE_BYTES + 64)  // 184384
#define NITEMS (OPC * (DD / NT))          // 496 work items per step

// ---- scratch (device globals; no runtime allocation) ----
__device__ __nv_bfloat16 g_Khi[(size_t)OPC * DD * DD];
__device__ __nv_bfloat16 g_Klo[(size_t)OPC * DD * DD];
__device__ float         g_Y[(size_t)OPC * BB * DD];     // Y[o][b][k]
__device__ __nv_bfloat16 g_A[2 * BB * DD];               // [h_hi(64); h_lo(64)] x 1024
__device__ float         g_h[BB * DD];
__device__ float         g_W[NSTEP * BB * OPC];
__device__ float         g_gate[NSTEP * BB];
__device__ int           g_ctr[NSTEP];                   // work-steal tickets

// ---- helpers ----
static __device__ __forceinline__ uint32_t sptr(const void* p) {
    return (uint32_t)__cvta_generic_to_shared(p);
}
static __device__ __forceinline__ void cp16(void* s, const void* g) {
    asm volatile("cp.async.cg.shared.global [%0], [%1], 16;" :: "r"(sptr(s)), "l"(g));
}
static __device__ __forceinline__ void ldsm_x4(uint32_t r[4], uint32_t addr) {
    asm volatile("ldmatrix.sync.aligned.m8n8.x4.shared.b16 {%0,%1,%2,%3}, [%4];"
                 : "=r"(r[0]), "=r"(r[1]), "=r"(r[2]), "=r"(r[3]) : "r"(addr));
}
static __device__ __forceinline__ void ldsm_x4_t(uint32_t r[4], uint32_t addr) {
    asm volatile("ldmatrix.sync.aligned.m8n8.x4.trans.shared.b16 {%0,%1,%2,%3}, [%4];"
                 : "=r"(r[0]), "=r"(r[1]), "=r"(r[2]), "=r"(r[3]) : "r"(addr));
}
static __device__ __forceinline__ void mma16816(float c[4], const uint32_t a[4],
                                                uint32_t b0, uint32_t b1) {
    asm volatile("mma.sync.aligned.m16n8k16.row.col.f32.bf16.bf16.f32 "
                 "{%0,%1,%2,%3}, {%4,%5,%6,%7}, {%8,%9}, {%0,%1,%2,%3};"
                 : "+f"(c[0]), "+f"(c[1]), "+f"(c[2]), "+f"(c[3])
                 : "r"(a[0]), "r"(a[1]), "r"(a[2]), "r"(a[3]), "r"(b0), "r"(b1));
}

// ============================================================================
// 1) Split op_kernels fp32 -> bf16 hi/lo
// ============================================================================
__global__ void convert_kernel(const float* __restrict__ K) {
    const size_t n4 = (size_t)OPC * DD * DD / 4;
    const float4* K4 = (const float4*)K;
    uint2* Hhi = (uint2*)g_Khi;
    uint2* Hlo = (uint2*)g_Klo;
    for (size_t i = blockIdx.x * (size_t)blockDim.x + threadIdx.x; i < n4;
         i += (size_t)gridDim.x * blockDim.x) {
        float4 v = K4[i];
        float x[4] = {v.x, v.y, v.z, v.w};
        unsigned short hi[4], lo[4];
#pragma unroll
        for (int j = 0; j < 4; ++j) {
            __nv_bfloat16 h = __float2bfloat16(x[j]);
            __nv_bfloat16 l = __float2bfloat16(x[j] - __bfloat162float(h));
            hi[j] = __bfloat16_as_ushort(h);
            lo[j] = __bfloat16_as_ushort(l);
        }
        uint2 ph, pl;
        ph.x = (uint32_t)hi[0] | ((uint32_t)hi[1] << 16);
        ph.y = (uint32_t)hi[2] | ((uint32_t)hi[3] << 16);
        pl.x = (uint32_t)lo[0] | ((uint32_t)lo[1] << 16);
        pl.y = (uint32_t)lo[2] | ((uint32_t)lo[3] << 16);
        Hhi[i] = ph;
        Hlo[i] = pl;
    }
}

// ============================================================================
// 2) Softmax + gates (all steps). Also zero work-steal counters each replay.
// ============================================================================
__global__ void prep_kernel(const float* __restrict__ logits,
                            const float* __restrict__ operands) {
    if (blockIdx.x == 0 && threadIdx.x < NSTEP) g_ctr[threadIdx.x] = 0;
    int gw = (blockIdx.x * blockDim.x + threadIdx.x) >> 5;
    int lane = threadIdx.x & 31;
    if (gw >= BB * NSTEP) return;
    int b = gw >> 4, s = gw & 15;
    float x = (lane < OPC) ? logits[(b * 16 + s) * OPC + lane] : -INFINITY;
    float m = x;
#pragma unroll
    for (int d = 16; d; d >>= 1) m = fmaxf(m, __shfl_xor_sync(0xffffffffu, m, d));
    float e = (lane < OPC) ? expf(x - m) : 0.f;
    float sum = e;
#pragma unroll
    for (int d = 16; d; d >>= 1) sum += __shfl_xor_sync(0xffffffffu, sum, d);
    if (lane < OPC) g_W[((size_t)s * BB + b) * OPC + lane] = e / sum;
    if (lane == 0)
        g_gate[s * BB + b] = 1.f / (1.f + expf(-operands[(b * 16 + s) * 4 + 3]));
}

// ============================================================================
// 3) h := signal; build stacked bf16 hi/lo operand A.
// ============================================================================
__global__ void init_kernel(const float* __restrict__ signal) {
    int idx = blockIdx.x * blockDim.x + threadIdx.x;
    if (idx >= BB * DD) return;
    float h = signal[idx];
    g_h[idx] = h;
    int b = idx >> 10, k = idx & 1023;
    __nv_bfloat16 hi = __float2bfloat16(h);
    g_A[idx] = hi;
    g_A[(BB + b) * DD + k] = __float2bfloat16(h - __bfloat162float(hi));
}

// ============================================================================
// 4) Persistent work-stealing GEMM. Item = (o, 64-wide n-tile). 496 items.
//    Warps 0-7:  [h_hi;h_lo](128 x d) @ K_hi -> 128x64
//    Warps 8-11:  h_hi(64 x d)        @ K_lo ->  64x64
//    5-stage cp.async pipeline, deterministic 3-phase smem reduction.
// ============================================================================
__device__ __forceinline__ void load_stage(char* smem, int s, int it, int tid,
                                           int n0, const __nv_bfloat16* Kh,
                                           const __nv_bfloat16* Kl) {
    char* base = smem + s * STAGE_BYTES;
    __nv_bfloat16* sA  = (__nv_bfloat16*)base;
    __nv_bfloat16* sBh = (__nv_bfloat16*)(base + A_BYTES);
    __nv_bfloat16* sBl = (__nv_bfloat16*)(base + A_BYTES + B_BYTES);
    const int d0 = it * KT;
    // A: 128 rows x 64 cols (16B chunks): 1024 ops
    for (int id = tid; id < 1024; id += 384) {
        int r = id >> 3, c = (id & 7) * 8;
        cp16(sA + r * AP + c, g_A + r * DD + d0 + c);
    }
    // B: 64 rows(k) x 64 cols(n), hi + lo: 512 ops each
    for (int id = tid; id < 512; id += 384) {
        int r = id >> 3, c = (id & 7) * 8;
        size_t goff = (size_t)(d0 + r) * DD + n0 + c;
        cp16(sBh + r * BP + c, Kh + goff);
        cp16(sBl + r * BP + c, Kl + goff);
    }
}

__global__ void __launch_bounds__(384, 1) step_gemm_kernel(int t) {
    extern __shared__ char smem[];
    int* bc = (int*)(smem + NSTAGE * STAGE_BYTES);
    const int tid = threadIdx.x;
    const int w = tid >> 5, lane = tid & 31;

    const bool isP2 = (w >= 8);
    const int wl = isP2 ? (w - 8) : w;
    const int wm = (wl >> 1) * 32;     // P1: 0,32,64,96 ; P2: 0,32
    const int wn = (wl & 1) * 32;
    const int lr = lane & 15;
    const int lc = (lane >> 4) * 8;
    const int rb = lane >> 2;
    const int cb = (lane & 3) * 2;

    for (;;) {
        if (tid == 0) *bc = atomicAdd(&g_ctr[t], 1);
        __syncthreads();
        const int item = *bc;
        __syncthreads();
        if (item >= NITEMS) break;

        const int o = item >> 4;
        const int n0 = (item & 15) * NT;
        const __nv_bfloat16* Kh = g_Khi + (size_t)o * DD * DD;
        const __nv_bfloat16* Kl = g_Klo + (size_t)o * DD * DD;

        float acc[2][4][4];
#pragma unroll
        for (int i = 0; i < 2; ++i)
#pragma unroll
            for (int j = 0; j < 4; ++j)
#pragma unroll
                for (int r = 0; r < 4; ++r) acc[i][j][r] = 0.f;

        // prologue: 4 stages in flight
#pragma unroll
        for (int s = 0; s < NSTAGE - 1; ++s) {
            load_stage(smem, s, s, tid, n0, Kh, Kl);
            asm volatile("cp.async.commit_group;");
        }

        for (int it = 0; it < DD / KT; ++it) {
            asm volatile("cp.async.wait_group %0;" :: "n"(NSTAGE - 2));
            __syncthreads();
            // prefetch stage it+4 (overwrites stage computed at it-1; safe after sync)
            if (it + NSTAGE - 1 < DD / KT)
                load_stage(smem, (it + NSTAGE - 1) % NSTAGE, it + NSTAGE - 1, tid,
                           n0, Kh, Kl);
            asm volatile("cp.async.commit_group;");

            char* base = smem + (it % NSTAGE) * STAGE_BYTES;
            const __nv_bfloat16* sA = (const __nv_bfloat16*)base;
            const __nv_bfloat16* sB =
                (const __nv_bfloat16*)(base + A_BYTES + (isP2 ? B_BYTES : 0));

#pragma unroll
            for (int kb = 0; kb < KT / 16; ++kb) {
                uint32_t a[2][4];
#pragma unroll
                for (int mi = 0; mi < 2; ++mi)
                    ldsm_x4(a[mi], sptr(sA + (wm + mi * 16 + lr) * AP + kb * 16 + lc));
#pragma unroll
                for (int nj = 0; nj < 2; ++nj) {
                    uint32_t b[4];
                    ldsm_x4_t(b, sptr(sB + (kb * 16 + lr) * BP + wn + nj * 16 + lc));
                    mma16816(acc[0][nj * 2 + 0], a[0], b[0], b[1]);
                    mma16816(acc[0][nj * 2 + 1], a[0], b[2], b[3]);
                    mma16816(acc[1][nj * 2 + 0], a[1], b[0], b[1]);
                    mma16816(acc[1][nj * 2 + 1], a[1], b[2], b[3]);
                }
            }
            __syncthreads();
        }

        // ---- deterministic 3-phase reduction: red[64][68] overlays smem ----
        float* red = (float*)smem;

        if (!isP2 && wm < 64) {        // phase 1: h_hi @ K_hi (write)
#pragma unroll
            for (int mi = 0; mi < 2; ++mi)
#pragma unroll
                for (int nj = 0; nj < 4; ++nj)
#pragma unroll
                    for (int r = 0; r < 4; ++r) {
                        int row = wm + mi * 16 + rb + ((r >> 1) << 3);
                        int col = wn + nj * 8 + cb + (r & 1);
                        red[row * 68 + col] = acc[mi][nj][r];
                    }
        }
        __syncthreads();
        if (!isP2 && wm >= 64) {       // phase 2: h_lo @ K_hi (add)
#pragma unroll
            for (int mi = 0; mi < 2; ++mi)
#pragma unroll
                for (int nj = 0; nj < 4; ++nj)
#pragma unroll
                    for (int r = 0; r < 4; ++r) {
                        int row = wm - 64 + mi * 16 + rb + ((r >> 1) << 3);
                        int col = wn + nj * 8 + cb + (r & 1);
                        red[row * 68 + col] += acc[mi][nj][r];
                    }
        }
        __syncthreads();
        if (isP2) {                    // phase 3: h_hi @ K_lo (add)
#pragma unroll
            for (int mi = 0; mi < 2; ++mi)
#pragma unroll
                for (int nj = 0; nj < 4; ++nj)
#pragma unroll
                    for (int r = 0; r < 4; ++r) {
                        int row = wm + mi * 16 + rb + ((r >> 1) << 3);
                        int col = wn + nj * 8 + cb + (r & 1);
                        red[row * 68 + col] += acc[mi][nj][r];
                    }
        }
        __syncthreads();

        float* Yo = g_Y + (size_t)o * BB * DD + n0;
        for (int id = tid; id < BB * NT; id += 384) {
            int b = id >> 6, n = id & 63;
            Yo[(size_t)b * DD + n] = red[b * 68 + n];
        }
        __syncthreads();   // red fully read before next item's loads / bc write
    }
}

// ============================================================================
// 5) Per-step update: transformed = sum_o w*Y ; gate mix ; re-split h.
// ============================================================================
__global__ void step_update_kernel(int t, float* __restrict__ out, int final_step) {
    int idx = blockIdx.x * blockDim.x + threadIdx.x;
    if (idx >= BB * DD) return;
    int b = idx >> 10, k = idx & 1023;
    const float* wrow = g_W + ((size_t)t * BB + b) * OPC;
    float tr = 0.f;
#pragma unroll
    for (int o2 = 0; o2 < OPC; ++o2)
        tr = fmaf(wrow[o2], g_Y[((size_t)o2 * BB + b) * DD + k], tr);
    float g = g_gate[t * BB + b];
    float h = g_h[idx];
    float hn = g * tr + (1.f - g) * h;
    if (final_step) out[idx] = hn;
    else            g_h[idx] = hn;
    __nv_bfloat16 hi = __float2bfloat16(hn);
    g_A[idx] = hi;
    g_A[(BB + b) * DD + k] = __float2bfloat16(hn - __bfloat162float(hi));
}

// ============================================================================
// launch
// ============================================================================
extern "C" void kernel_launch(void* const* d_in, const int* in_sizes, int n_in,
                              void* d_out, int out_size) {
    const float* logits   = (const float*)d_in[0];
    const float* operands = (const float*)d_in[1];
    const float* signal   = (const float*)d_in[2];
    const float* opk      = (const float*)d_in[3];
    float* out = (float*)d_out;

    int nsm = 148;
    cudaDeviceGetAttribute(&nsm, cudaDevAttrMultiProcessorCount, 0);

    cudaFuncSetAttribute(step_gemm_kernel,
                         cudaFuncAttributeMaxDynamicSharedMemorySize, GEMM_SMEM);

    convert_kernel<<<4096, 256>>>(opk);
    prep_kernel<<<128, 256>>>(logits, operands);
    init_kernel<<<256, 256>>>(signal);
    for (int t = 0; t < NSTEP; ++t) {
        step_gemm_kernel<<<nsm, 384, GEMM_SMEM>>>(t);
        step_update_kernel<<<256, 256>>>(t, out, (t == NSTEP - 1) ? 1 : 0);
    }
}

// round 11
// speedup vs baseline: 1.2260x; 1.2260x over previous
#include <cuda_runtime.h>
#include <cuda_bf16.h>
#include <cstdint>

#define OPC 31
#define BB 64
#define DD 1024
#define NSTEP 16

// ---- GEMM tiling ----
#define KT 64              // k-chunk (over d)
#define NT 64              // n-tile width
#define AP 72              // A smem row stride (144B = 9*16B, ldmatrix conflict-free)
#define BP 72              // B smem row stride
#define A_BYTES (128 * AP * 2)               // 18432
#define B_BYTES (KT * BP * 2)                // 9216 per (hi|lo)
#define STAGE_BYTES (A_BYTES + 2 * B_BYTES)  // 36864
#define NSTAGE 3
#define GEMM_SMEM (NSTAGE * STAGE_BYTES + 64)  // 110656 -> 2 CTAs/SM
#define NITEMS (OPC * (DD / NT))             // 496 work items per step

// ---- scratch (device globals; no runtime allocation) ----
__device__ __nv_bfloat16 g_Khi[(size_t)OPC * DD * DD];
__device__ __nv_bfloat16 g_Klo[(size_t)OPC * DD * DD];
__device__ float         g_Y[(size_t)OPC * BB * DD];     // Y[o][b][k]
__device__ __nv_bfloat16 g_A[2 * BB * DD];               // [h_hi(64); h_lo(64)] x 1024
__device__ float         g_h[BB * DD];
__device__ float         g_W[NSTEP * BB * OPC];
__device__ float         g_gate[NSTEP * BB];
__device__ int           g_ctr[NSTEP];                   // work-steal tickets

// ---- helpers ----
static __device__ __forceinline__ uint32_t sptr(const void* p) {
    return (uint32_t)__cvta_generic_to_shared(p);
}
static __device__ __forceinline__ void cp16(void* s, const void* g) {
    asm volatile("cp.async.cg.shared.global [%0], [%1], 16;" :: "r"(sptr(s)), "l"(g));
}
static __device__ __forceinline__ void ldsm_x4(uint32_t r[4], uint32_t addr) {
    asm volatile("ldmatrix.sync.aligned.m8n8.x4.shared.b16 {%0,%1,%2,%3}, [%4];"
                 : "=r"(r[0]), "=r"(r[1]), "=r"(r[2]), "=r"(r[3]) : "r"(addr));
}
static __device__ __forceinline__ void ldsm_x4_t(uint32_t r[4], uint32_t addr) {
    asm volatile("ldmatrix.sync.aligned.m8n8.x4.trans.shared.b16 {%0,%1,%2,%3}, [%4];"
                 : "=r"(r[0]), "=r"(r[1]), "=r"(r[2]), "=r"(r[3]) : "r"(addr));
}
static __device__ __forceinline__ void mma16816(float c[4], const uint32_t a[4],
                                                uint32_t b0, uint32_t b1) {
    asm volatile("mma.sync.aligned.m16n8k16.row.col.f32.bf16.bf16.f32 "
                 "{%0,%1,%2,%3}, {%4,%5,%6,%7}, {%8,%9}, {%0,%1,%2,%3};"
                 : "+f"(c[0]), "+f"(c[1]), "+f"(c[2]), "+f"(c[3])
                 : "r"(a[0]), "r"(a[1]), "r"(a[2]), "r"(a[3]), "r"(b0), "r"(b1));
}

// ============================================================================
// 1) Split op_kernels fp32 -> bf16 hi/lo
// ============================================================================
__global__ void convert_kernel(const float* __restrict__ K) {
    const size_t n4 = (size_t)OPC * DD * DD / 4;
    const float4* K4 = (const float4*)K;
    uint2* Hhi = (uint2*)g_Khi;
    uint2* Hlo = (uint2*)g_Klo;
    for (size_t i = blockIdx.x * (size_t)blockDim.x + threadIdx.x; i < n4;
         i += (size_t)gridDim.x * blockDim.x) {
        float4 v = K4[i];
        float x[4] = {v.x, v.y, v.z, v.w};
        unsigned short hi[4], lo[4];
#pragma unroll
        for (int j = 0; j < 4; ++j) {
            __nv_bfloat16 h = __float2bfloat16(x[j]);
            __nv_bfloat16 l = __float2bfloat16(x[j] - __bfloat162float(h));
            hi[j] = __bfloat16_as_ushort(h);
            lo[j] = __bfloat16_as_ushort(l);
        }
        uint2 ph, pl;
        ph.x = (uint32_t)hi[0] | ((uint32_t)hi[1] << 16);
        ph.y = (uint32_t)hi[2] | ((uint32_t)hi[3] << 16);
        pl.x = (uint32_t)lo[0] | ((uint32_t)lo[1] << 16);
        pl.y = (uint32_t)lo[2] | ((uint32_t)lo[3] << 16);
        Hhi[i] = ph;
        Hlo[i] = pl;
    }
}

// ============================================================================
// 2) Softmax + gates (all steps). Also zero work-steal counters each replay.
// ============================================================================
__global__ void prep_kernel(const float* __restrict__ logits,
                            const float* __restrict__ operands) {
    if (blockIdx.x == 0 && threadIdx.x < NSTEP) g_ctr[threadIdx.x] = 0;
    int gw = (blockIdx.x * blockDim.x + threadIdx.x) >> 5;
    int lane = threadIdx.x & 31;
    if (gw >= BB * NSTEP) return;
    int b = gw >> 4, s = gw & 15;
    float x = (lane < OPC) ? logits[(b * 16 + s) * OPC + lane] : -INFINITY;
    float m = x;
#pragma unroll
    for (int d = 16; d; d >>= 1) m = fmaxf(m, __shfl_xor_sync(0xffffffffu, m, d));
    float e = (lane < OPC) ? expf(x - m) : 0.f;
    float sum = e;
#pragma unroll
    for (int d = 16; d; d >>= 1) sum += __shfl_xor_sync(0xffffffffu, sum, d);
    if (lane < OPC) g_W[((size_t)s * BB + b) * OPC + lane] = e / sum;
    if (lane == 0)
        g_gate[s * BB + b] = 1.f / (1.f + expf(-operands[(b * 16 + s) * 4 + 3]));
}

// ============================================================================
// 3) h := signal; build stacked bf16 hi/lo operand A.
// ============================================================================
__global__ void init_kernel(const float* __restrict__ signal) {
    int idx = blockIdx.x * blockDim.x + threadIdx.x;
    if (idx >= BB * DD) return;
    float h = signal[idx];
    g_h[idx] = h;
    int b = idx >> 10, k = idx & 1023;
    __nv_bfloat16 hi = __float2bfloat16(h);
    g_A[idx] = hi;
    g_A[(BB + b) * DD + k] = __float2bfloat16(h - __bfloat162float(hi));
}

// ============================================================================
// 4) Persistent work-stealing GEMM, 2 CTAs/SM. Item = (o, 64-wide n-tile).
//    Warps 0-7:  [h_hi;h_lo](128 x d) @ K_hi -> 128x64
//    Warps 8-11:  h_hi(64 x d)        @ K_lo ->  64x64
//    3-stage cp.async pipeline; single-sync 3-buffer epilogue reduction.
// ============================================================================
__device__ __forceinline__ void load_stage(char* smem, int s, int it, int tid,
                                           int n0, const __nv_bfloat16* Kh,
                                           const __nv_bfloat16* Kl) {
    char* base = smem + s * STAGE_BYTES;
    __nv_bfloat16* sA  = (__nv_bfloat16*)base;
    __nv_bfloat16* sBh = (__nv_bfloat16*)(base + A_BYTES);
    __nv_bfloat16* sBl = (__nv_bfloat16*)(base + A_BYTES + B_BYTES);
    const int d0 = it * KT;
    for (int id = tid; id < 1024; id += 384) {      // A: 128 x 64
        int r = id >> 3, c = (id & 7) * 8;
        cp16(sA + r * AP + c, g_A + r * DD + d0 + c);
    }
    for (int id = tid; id < 512; id += 384) {       // B: 64(k) x 64(n), hi+lo
        int r = id >> 3, c = (id & 7) * 8;
        size_t goff = (size_t)(d0 + r) * DD + n0 + c;
        cp16(sBh + r * BP + c, Kh + goff);
        cp16(sBl + r * BP + c, Kl + goff);
    }
}

__global__ void __launch_bounds__(384, 2) step_gemm_kernel(int t) {
    extern __shared__ char smem[];
    int* bc = (int*)(smem + NSTAGE * STAGE_BYTES);
    const int tid = threadIdx.x;
    const int w = tid >> 5, lane = tid & 31;

    const bool isP2 = (w >= 8);
    const int wl = isP2 ? (w - 8) : w;
    const int wm = (wl >> 1) * 32;     // P1: 0,32,64,96 ; P2: 0,32
    const int wn = (wl & 1) * 32;
    const int lr = lane & 15;
    const int lc = (lane >> 4) * 8;
    const int rb = lane >> 2;
    const int cb = (lane & 3) * 2;

    for (;;) {
        if (tid == 0) *bc = atomicAdd(&g_ctr[t], 1);
        __syncthreads();
        const int item = *bc;
        __syncthreads();
        if (item >= NITEMS) break;

        const int o = item >> 4;
        const int n0 = (item & 15) * NT;
        const __nv_bfloat16* Kh = g_Khi + (size_t)o * DD * DD;
        const __nv_bfloat16* Kl = g_Klo + (size_t)o * DD * DD;

        float acc[2][4][4];
#pragma unroll
        for (int i = 0; i < 2; ++i)
#pragma unroll
            for (int j = 0; j < 4; ++j)
#pragma unroll
                for (int r = 0; r < 4; ++r) acc[i][j][r] = 0.f;

#pragma unroll
        for (int s = 0; s < NSTAGE - 1; ++s) {      // 2 stages in flight
            load_stage(smem, s, s, tid, n0, Kh, Kl);
            asm volatile("cp.async.commit_group;");
        }

        for (int it = 0; it < DD / KT; ++it) {
            asm volatile("cp.async.wait_group %0;" :: "n"(NSTAGE - 2));
            __syncthreads();
            if (it + NSTAGE - 1 < DD / KT)
                load_stage(smem, (it + NSTAGE - 1) % NSTAGE, it + NSTAGE - 1, tid,
                           n0, Kh, Kl);
            asm volatile("cp.async.commit_group;");

            char* base = smem + (it % NSTAGE) * STAGE_BYTES;
            const __nv_bfloat16* sA = (const __nv_bfloat16*)base;
            const __nv_bfloat16* sB =
                (const __nv_bfloat16*)(base + A_BYTES + (isP2 ? B_BYTES : 0));

#pragma unroll
            for (int kb = 0; kb < KT / 16; ++kb) {
                uint32_t a[2][4];
#pragma unroll
                for (int mi = 0; mi < 2; ++mi)
                    ldsm_x4(a[mi], sptr(sA + (wm + mi * 16 + lr) * AP + kb * 16 + lc));
#pragma unroll
                for (int nj = 0; nj < 2; ++nj) {
                    uint32_t b[4];
                    ldsm_x4_t(b, sptr(sB + (kb * 16 + lr) * BP + wn + nj * 16 + lc));
                    mma16816(acc[0][nj * 2 + 0], a[0], b[0], b[1]);
                    mma16816(acc[0][nj * 2 + 1], a[0], b[2], b[3]);
                    mma16816(acc[1][nj * 2 + 0], a[1], b[0], b[1]);
                    mma16816(acc[1][nj * 2 + 1], a[1], b[2], b[3]);
                }
            }
            __syncthreads();
        }

        // ---- epilogue: 3 disjoint buffers, ONE sync, summed store ----
        // red1 = hi*Khi (P1 warps wm<64), red2 = lo*Khi (P1 wm>=64), red3 = hi*Klo (P2)
        float* red1 = (float*)smem;
        float* red2 = red1 + 64 * 68;
        float* red3 = red2 + 64 * 68;
        float* dst = isP2 ? red3 : (wm < 64 ? red1 : red2);
        const int rowbase = isP2 ? wm : (wm < 64 ? wm : wm - 64);
#pragma unroll
        for (int mi = 0; mi < 2; ++mi)
#pragma unroll
            for (int nj = 0; nj < 4; ++nj)
#pragma unroll
                for (int r = 0; r < 4; ++r) {
                    int row = rowbase + mi * 16 + rb + ((r >> 1) << 3);
                    int col = wn + nj * 8 + cb + (r & 1);
                    dst[row * 68 + col] = acc[mi][nj][r];
                }
        __syncthreads();

        float* Yo = g_Y + (size_t)o * BB * DD + n0;
        for (int id = tid; id < BB * NT; id += 384) {
            int b = id >> 6, n = id & 63;
            int off = b * 68 + n;
            Yo[(size_t)b * DD + n] = red1[off] + red2[off] + red3[off];
        }
        __syncthreads();   // buffers fully read before next item's loads / bc write
    }
}

// ============================================================================
// 5) Per-step update: transformed = sum_o w*Y ; gate mix ; re-split h.
// ============================================================================
__global__ void step_update_kernel(int t, float* __restrict__ out, int final_step) {
    int idx = blockIdx.x * blockDim.x + threadIdx.x;
    if (idx >= BB * DD) return;
    int b = idx >> 10, k = idx & 1023;
    const float* wrow = g_W + ((size_t)t * BB + b) * OPC;
    float tr = 0.f;
#pragma unroll
    for (int o2 = 0; o2 < OPC; ++o2)
        tr = fmaf(wrow[o2], g_Y[((size_t)o2 * BB + b) * DD + k], tr);
    float g = g_gate[t * BB + b];
    float h = g_h[idx];
    float hn = g * tr + (1.f - g) * h;
    if (final_step) out[idx] = hn;
    else            g_h[idx] = hn;
    __nv_bfloat16 hi = __float2bfloat16(hn);
    g_A[idx] = hi;
    g_A[(BB + b) * DD + k] = __float2bfloat16(hn - __bfloat162float(hi));
}

// ============================================================================
// launch
// ============================================================================
extern "C" void kernel_launch(void* const* d_in, const int* in_sizes, int n_in,
                              void* d_out, int out_size) {
    const float* logits   = (const float*)d_in[0];
    const float* operands = (const float*)d_in[1];
    const float* signal   = (const float*)d_in[2];
    const float* opk      = (const float*)d_in[3];
    float* out = (float*)d_out;

    int nsm = 148;
    cudaDeviceGetAttribute(&nsm, cudaDevAttrMultiProcessorCount, 0);

    cudaFuncSetAttribute(step_gemm_kernel,
                         cudaFuncAttributeMaxDynamicSharedMemorySize, GEMM_SMEM);

    convert_kernel<<<4096, 256>>>(opk);
    prep_kernel<<<128, 256>>>(logits, operands);
    init_kernel<<<256, 256>>>(signal);
    for (int t = 0; t < NSTEP; ++t) {
        step_gemm_kernel<<<2 * nsm, 384, GEMM_SMEM>>>(t);
        step_update_kernel<<<256, 256>>>(t, out, (t == NSTEP - 1) ? 1 : 0);
    }
}

// round 13
// speedup vs baseline: 1.4506x; 1.1832x over previous
#include <cuda_runtime.h>
#include <cuda_bf16.h>
#include <cstdint>

#define OPC 31
#define BB 64
#define DD 1024
#define NSTEP 16

// ---- GEMM tiling ----
#define KT 64                      // k-chunk (over d)
#define NT 64                      // n-tile width
#define A_TILE 16384               // 128 rows x 64 cols bf16 (pre-swizzled)
#define B_TILE 8192                // 64 rows x 64 cols bf16 (pre-swizzled)
#define STG_BYTES (A_TILE + 2 * B_TILE)   // 32768
#define NSTAGE 3
#define SMEM_STAGES (NSTAGE * STG_BYTES)  // 98304
#define MBAR_FULL  (SMEM_STAGES)          // 3 x 8B
#define MBAR_EMPTY (SMEM_STAGES + 24)     // 3 x 8B
#define BC_OFF     (SMEM_STAGES + 48)
#define GEMM_SMEM  (SMEM_STAGES + 64)
#define NITEMS (OPC * (DD / NT))          // 496
#define NTHR 416                          // 12 consumer warps + 1 producer warp

#define SWZ(o) ((o) ^ (((o) >> 3) & 0x70))

// ---- scratch (device globals; no runtime allocation) ----
__device__ __nv_bfloat16 g_Bhi[(size_t)OPC * 16 * 16 * 4096];  // packed 8KB tiles
__device__ __nv_bfloat16 g_Blo[(size_t)OPC * 16 * 16 * 4096];
__device__ __nv_bfloat16 g_Apk[16 * 8192];                     // 16 x 16KB chunks
__device__ float         g_Y[(size_t)OPC * BB * DD];           // Y[o][b][k]
__device__ float         g_h[BB * DD];
__device__ float         g_W[NSTEP * BB * OPC];
__device__ float         g_gate[NSTEP * BB];
__device__ int           g_ctr[NSTEP];

// ---- helpers ----
static __device__ __forceinline__ uint32_t sptr(const void* p) {
    return (uint32_t)__cvta_generic_to_shared(p);
}
static __device__ __forceinline__ void mbar_init(uint32_t bar, uint32_t cnt) {
    asm volatile("mbarrier.init.shared.b64 [%0], %1;" :: "r"(bar), "r"(cnt) : "memory");
}
static __device__ __forceinline__ void mbar_arrive(uint32_t bar) {
    asm volatile("mbarrier.arrive.shared.b64 _, [%0];" :: "r"(bar) : "memory");
}
static __device__ __forceinline__ void mbar_expect_tx(uint32_t bar, uint32_t bytes) {
    asm volatile("mbarrier.arrive.expect_tx.shared.b64 _, [%0], %1;"
                 :: "r"(bar), "r"(bytes) : "memory");
}
static __device__ __forceinline__ void mbar_wait_acq(uint32_t bar, uint32_t phase) {
    asm volatile(
        "{\n\t.reg .pred P;\n"
        "W_%=:\n\t"
        "mbarrier.try_wait.parity.acquire.cta.shared::cta.b64 P, [%0], %1, 0x989680;\n\t"
        "@P bra.uni D_%=;\n\t"
        "bra.uni W_%=;\n"
        "D_%=:\n\t}"
        :: "r"(bar), "r"(phase) : "memory");
}
static __device__ __forceinline__ void mbar_wait_rlx(uint32_t bar, uint32_t phase) {
    asm volatile(
        "{\n\t.reg .pred P;\n"
        "W_%=:\n\t"
        "mbarrier.try_wait.parity.relaxed.cta.shared::cta.b64 P, [%0], %1, 0x989680;\n\t"
        "@P bra.uni D_%=;\n\t"
        "bra.uni W_%=;\n"
        "D_%=:\n\t}"
        :: "r"(bar), "r"(phase) : "memory");
}
static __device__ __forceinline__ void bulkcp(uint32_t dst, const void* src,
                                              uint32_t bytes, uint32_t mbar) {
    asm volatile(
        "cp.async.bulk.shared::cluster.global.mbarrier::complete_tx::bytes "
        "[%0], [%1], %2, [%3];"
        :: "r"(dst), "l"(src), "r"(bytes), "r"(mbar) : "memory");
}
static __device__ __forceinline__ void ldsm_x4(uint32_t r[4], uint32_t addr) {
    asm volatile("ldmatrix.sync.aligned.m8n8.x4.shared.b16 {%0,%1,%2,%3}, [%4];"
                 : "=r"(r[0]), "=r"(r[1]), "=r"(r[2]), "=r"(r[3]) : "r"(addr));
}
static __device__ __forceinline__ void ldsm_x4_t(uint32_t r[4], uint32_t addr) {
    asm volatile("ldmatrix.sync.aligned.m8n8.x4.trans.shared.b16 {%0,%1,%2,%3}, [%4];"
                 : "=r"(r[0]), "=r"(r[1]), "=r"(r[2]), "=r"(r[3]) : "r"(addr));
}
static __device__ __forceinline__ void mma16816(float c[4], const uint32_t a[4],
                                                uint32_t b0, uint32_t b1) {
    asm volatile("mma.sync.aligned.m16n8k16.row.col.f32.bf16.bf16.f32 "
                 "{%0,%1,%2,%3}, {%4,%5,%6,%7}, {%8,%9}, {%0,%1,%2,%3};"
                 : "+f"(c[0]), "+f"(c[1]), "+f"(c[2]), "+f"(c[3])
                 : "r"(a[0]), "r"(a[1]), "r"(a[2]), "r"(a[3]), "r"(b0), "r"(b1));
}

// ============================================================================
// 1) Split op_kernels fp32 -> packed, pre-swizzled bf16 hi/lo tiles.
//    Tile (o, nt, kc): 64 rows(k) x 64 cols(n), row stride 128B, SW128 swizzle.
// ============================================================================
__global__ void convert_kernel(const float* __restrict__ K) {
    const size_t n4 = (size_t)OPC * DD * DD / 4;
    const float4* K4 = (const float4*)K;
    char* Bh = (char*)g_Bhi;
    char* Bl = (char*)g_Blo;
    for (size_t i = blockIdx.x * (size_t)blockDim.x + threadIdx.x; i < n4;
         i += (size_t)gridDim.x * blockDim.x) {
        int o = (int)(i / (DD * DD / 4));
        int rem = (int)(i % (DD * DD / 4));
        int d = rem >> 8;            // DD/4 = 256 groups per row
        int n = (rem & 255) * 4;
        float4 v = K4[i];
        float x[4] = {v.x, v.y, v.z, v.w};
        unsigned short hi[4], lo[4];
#pragma unroll
        for (int j = 0; j < 4; ++j) {
            __nv_bfloat16 h = __float2bfloat16(x[j]);
            __nv_bfloat16 l = __float2bfloat16(x[j] - __bfloat162float(h));
            hi[j] = __bfloat16_as_ushort(h);
            lo[j] = __bfloat16_as_ushort(l);
        }
        uint2 ph, pl;
        ph.x = (uint32_t)hi[0] | ((uint32_t)hi[1] << 16);
        ph.y = (uint32_t)hi[2] | ((uint32_t)hi[3] << 16);
        pl.x = (uint32_t)lo[0] | ((uint32_t)lo[1] << 16);
        pl.y = (uint32_t)lo[2] | ((uint32_t)lo[3] << 16);
        int kc = d >> 6, kr = d & 63, nt = n >> 6, nc = n & 63;
        size_t tile = ((size_t)(o * 16 + nt) * 16 + kc) * B_TILE;
        uint32_t off = SWZ((uint32_t)(kr * 128 + nc * 2));   // 8B aligned, preserved
        *(uint2*)(Bh + tile + off) = ph;
        *(uint2*)(Bl + tile + off) = pl;
    }
}

// ============================================================================
// 2) Softmax + gates; zero tickets each replay.
// ============================================================================
__global__ void prep_kernel(const float* __restrict__ logits,
                            const float* __restrict__ operands) {
    if (blockIdx.x == 0 && threadIdx.x < NSTEP) g_ctr[threadIdx.x] = 0;
    int gw = (blockIdx.x * blockDim.x + threadIdx.x) >> 5;
    int lane = threadIdx.x & 31;
    if (gw >= BB * NSTEP) return;
    int b = gw >> 4, s = gw & 15;
    float x = (lane < OPC) ? logits[(b * 16 + s) * OPC + lane] : -INFINITY;
    float m = x;
#pragma unroll
    for (int d = 16; d; d >>= 1) m = fmaxf(m, __shfl_xor_sync(0xffffffffu, m, d));
    float e = (lane < OPC) ? expf(x - m) : 0.f;
    float sum = e;
#pragma unroll
    for (int d = 16; d; d >>= 1) sum += __shfl_xor_sync(0xffffffffu, sum, d);
    if (lane < OPC) g_W[((size_t)s * BB + b) * OPC + lane] = e / sum;
    if (lane == 0)
        g_gate[s * BB + b] = 1.f / (1.f + expf(-operands[(b * 16 + s) * 4 + 3]));
}

// ---- A-pack write: row b (hi) / row 64+b (lo), chunk kc, col c; swizzled ----
static __device__ __forceinline__ void write_Apk(int b, int k, float hval) {
    char* A = (char*)g_Apk;
    int kc = k >> 6, c = k & 63;
    __nv_bfloat16 hi = __float2bfloat16(hval);
    __nv_bfloat16 lo = __float2bfloat16(hval - __bfloat162float(hi));
    uint32_t off_hi = SWZ((uint32_t)(b * 128 + c * 2));
    uint32_t off_lo = SWZ((uint32_t)((64 + b) * 128 + c * 2));
    *(unsigned short*)(A + (size_t)kc * A_TILE + off_hi) = __bfloat16_as_ushort(hi);
    *(unsigned short*)(A + (size_t)kc * A_TILE + off_lo) = __bfloat16_as_ushort(lo);
}

// ============================================================================
// 3) h := signal; build packed A.
// ============================================================================
__global__ void init_kernel(const float* __restrict__ signal) {
    int idx = blockIdx.x * blockDim.x + threadIdx.x;
    if (idx >= BB * DD) return;
    float h = signal[idx];
    g_h[idx] = h;
    write_Apk(idx >> 10, idx & 1023, h);
}

// ============================================================================
// 4) Persistent GEMM: bulk-copy (UBLKCP) pipeline, mbarrier-paced.
//    Warp 12 = producer (3 bulk copies / stage). Warps 0-11 = consumers:
//      0-7:  [h_hi;h_lo](128) @ K_hi ; 8-11: h_hi(64) @ K_lo.
// ============================================================================
__global__ void __launch_bounds__(NTHR, 2) step_gemm_kernel(int t) {
    extern __shared__ __align__(128) char smem[];
    const uint32_t sbase = sptr(smem);
    int* bc = (int*)(smem + BC_OFF);
    const int tid = threadIdx.x;
    const int w = tid >> 5, lane = tid & 31;

    if (tid == 0) {
#pragma unroll
        for (int s = 0; s < NSTAGE; ++s) {
            mbar_init(sbase + MBAR_FULL + s * 8, 1);    // expect_tx arrival
            mbar_init(sbase + MBAR_EMPTY + s * 8, 12);  // one per consumer warp
        }
    }
    __syncthreads();

    const bool isProd = (w == 12);
    const bool isP2 = (w >= 8) && !isProd;
    const int wl = isP2 ? (w - 8) : w;
    const int wm = (wl >> 1) * 32;      // P1: 0,32,64,96 ; P2: 0,32
    const int wn = (wl & 1) * 32;
    const int lr = lane & 15;
    const int lc = (lane >> 4) * 8;
    const int rb = lane >> 2;
    const int cb = (lane & 3) * 2;

    // persistent pipeline cursors
    int pst = 0; uint32_t pph = 1;      // producer on empty barriers
    int cst = 0; uint32_t cph = 0;      // consumers on full barriers

    // per-lane invariant byte offsets (pre-swizzle)
    const uint32_t aRow = (uint32_t)((wm + lr) * 128 + lc * 2);
    const uint32_t bRow = (uint32_t)(lr * 128 + (wn + lc) * 2);

    for (;;) {
        if (tid == 0) *bc = atomicAdd(&g_ctr[t], 1);
        __syncthreads();
        const int item = *bc;
        __syncthreads();
        if (item >= NITEMS) break;

        const int o = item >> 4;
        const int nt = item & 15;
        const char* gBh = (const char*)g_Bhi + ((size_t)(o * 16 + nt) * 16) * B_TILE;
        const char* gBl = (const char*)g_Blo + ((size_t)(o * 16 + nt) * 16) * B_TILE;
        const char* gA  = (const char*)g_Apk;

        float acc[2][4][4];
#pragma unroll
        for (int i = 0; i < 2; ++i)
#pragma unroll
            for (int j = 0; j < 4; ++j)
#pragma unroll
                for (int r = 0; r < 4; ++r) acc[i][j][r] = 0.f;

        if (isProd) {
            if (lane == 0) {
                for (int pc = 0; pc < 16; ++pc) {
                    uint32_t eb = sbase + MBAR_EMPTY + pst * 8;
                    uint32_t fb = sbase + MBAR_FULL + pst * 8;
                    mbar_wait_rlx(eb, pph);
                    mbar_expect_tx(fb, STG_BYTES);
                    uint32_t dst = sbase + pst * STG_BYTES;
                    bulkcp(dst,              gA  + (size_t)pc * A_TILE, A_TILE, fb);
                    bulkcp(dst + A_TILE,     gBh + (size_t)pc * B_TILE, B_TILE, fb);
                    bulkcp(dst + A_TILE + B_TILE, gBl + (size_t)pc * B_TILE, B_TILE, fb);
                    if (++pst == NSTAGE) { pst = 0; pph ^= 1; }
                }
            }
        } else {
            for (int kc = 0; kc < 16; ++kc) {
                uint32_t fb = sbase + MBAR_FULL + cst * 8;
                mbar_wait_acq(fb, cph);
                uint32_t aB = sbase + cst * STG_BYTES;
                uint32_t bB = aB + A_TILE + (isP2 ? B_TILE : 0);
#pragma unroll
                for (int kb = 0; kb < 4; ++kb) {
                    uint32_t a[2][4];
#pragma unroll
                    for (int mi = 0; mi < 2; ++mi)
                        ldsm_x4(a[mi], aB + SWZ(aRow + mi * 2048 + kb * 32));
#pragma unroll
                    for (int nj = 0; nj < 2; ++nj) {
                        uint32_t b[4];
                        ldsm_x4_t(b, bB + SWZ(bRow + kb * 2048 + nj * 32));
                        mma16816(acc[0][nj * 2 + 0], a[0], b[0], b[1]);
                        mma16816(acc[0][nj * 2 + 1], a[0], b[2], b[3]);
                        mma16816(acc[1][nj * 2 + 0], a[1], b[0], b[1]);
                        mma16816(acc[1][nj * 2 + 1], a[1], b[2], b[3]);
                    }
                }
                __syncwarp();
                if (lane == 0) mbar_arrive(sbase + MBAR_EMPTY + cst * 8);
                if (++cst == NSTAGE) { cst = 0; cph ^= 1; }
            }
        }
        __syncthreads();   // all copies landed & consumed; stage smem reusable

        // ---- epilogue: 3 disjoint red buffers overlay stage smem, one sync ----
        float* red1 = (float*)smem;            // hi*Khi
        float* red2 = red1 + 64 * 68;          // lo*Khi
        float* red3 = red2 + 64 * 68;          // hi*Klo
        if (!isProd) {
            float* dst = isP2 ? red3 : (wm < 64 ? red1 : red2);
            const int rowbase = isP2 ? wm : (wm < 64 ? wm : wm - 64);
#pragma unroll
            for (int mi = 0; mi < 2; ++mi)
#pragma unroll
                for (int nj = 0; nj < 4; ++nj)
#pragma unroll
                    for (int r = 0; r < 4; ++r) {
                        int row = rowbase + mi * 16 + rb + ((r >> 1) << 3);
                        int col = wn + nj * 8 + cb + (r & 1);
                        dst[row * 68 + col] = acc[mi][nj][r];
                    }
        }
        __syncthreads();

        float* Yo = g_Y + (size_t)o * BB * DD + nt * NT;
        for (int id = tid; id < BB * NT; id += NTHR) {
            int b = id >> 6, n = id & 63;
            int off = b * 68 + n;
            Yo[(size_t)b * DD + n] = red1[off] + red2[off] + red3[off];
        }
        __syncthreads();   // red fully read before next item's bulk fills
    }
}

// ============================================================================
// 5) Per-step update: transformed = sum_o w*Y ; gate mix ; re-pack A.
// ============================================================================
__global__ void step_update_kernel(int t, float* __restrict__ out, int final_step) {
    int idx = blockIdx.x * blockDim.x + threadIdx.x;
    if (idx >= BB * DD) return;
    int b = idx >> 10, k = idx & 1023;
    const float* wrow = g_W + ((size_t)t * BB + b) * OPC;
    float tr = 0.f;
#pragma unroll
    for (int o2 = 0; o2 < OPC; ++o2)
        tr = fmaf(wrow[o2], g_Y[((size_t)o2 * BB + b) * DD + k], tr);
    float g = g_gate[t * BB + b];
    float h = g_h[idx];
    float hn = g * tr + (1.f - g) * h;
    if (final_step) out[idx] = hn;
    else            g_h[idx] = hn;
    write_Apk(b, k, hn);
}

// ============================================================================
// launch
// ============================================================================
extern "C" void kernel_launch(void* const* d_in, const int* in_sizes, int n_in,
                              void* d_out, int out_size) {
    const float* logits   = (const float*)d_in[0];
    const float* operands = (const float*)d_in[1];
    const float* signal   = (const float*)d_in[2];
    const float* opk      = (const float*)d_in[3];
    float* out = (float*)d_out;

    int nsm = 148;
    cudaDeviceGetAttribute(&nsm, cudaDevAttrMultiProcessorCount, 0);

    cudaFuncSetAttribute(step_gemm_kernel,
                         cudaFuncAttributeMaxDynamicSharedMemorySize, GEMM_SMEM);

    convert_kernel<<<4096, 256>>>(opk);
    prep_kernel<<<128, 256>>>(logits, operands);
    init_kernel<<<256, 256>>>(signal);
    for (int t = 0; t < NSTEP; ++t) {
        step_gemm_kernel<<<2 * nsm, NTHR, GEMM_SMEM>>>(t);
        step_update_kernel<<<256, 256>>>(t, out, (t == NSTEP - 1) ? 1 : 0);
    }
}